// round 17
// baseline (speedup 1.0000x reference)
#include <cuda_runtime.h>
#include <mma.h>
#include <cuda_fp16.h>
#include <math.h>

using namespace nvcuda;

#define Bsz 4096
#define Dd  1024
#define Rr  256

// ---------------- device scratch ----------------
static __device__ float  g_hx[(size_t)Bsz * Rr];
static __device__ float  g_hv[(size_t)Bsz * Rr];
static __device__ float  g_fU[(size_t)Bsz * Rr];
static __device__ float  g_P [(size_t)Bsz * Rr];
static __device__ float  g_WUp[(size_t)8 * Rr * Rr];
static __device__ __align__(16) __half g_Xh[(size_t)Bsz * Dd];
static __device__ __align__(16) __half g_Vh[(size_t)Bsz * Dd];
static __device__ __align__(16) __half g_Fh[(size_t)Bsz * Dd];
static __device__ __align__(16) __half g_Uh[(size_t)Dd * Rr];
static __device__ __align__(16) __half g_Wh[(size_t)Rr * Dd];
static __device__ __align__(16) __half g_WUh[(size_t)Rr * Rr];

// ---------------- helpers ----------------
__device__ __forceinline__ void cp_async16(void* sptr, const void* gptr) {
    unsigned s = (unsigned)__cvta_generic_to_shared(sptr);
    asm volatile("cp.async.cg.shared.global [%0], [%1], 16;\n" :: "r"(s), "l"(gptr));
}
__device__ __forceinline__ void cp_commit() { asm volatile("cp.async.commit_group;\n"); }
template <int N> __device__ __forceinline__ void cp_wait() {
    asm volatile("cp.async.wait_group %0;\n" :: "n"(N));
}
__device__ __forceinline__ float tanh_fast(float x) {
    float y; asm("tanh.approx.f32 %0, %1;" : "=f"(y) : "f"(x)); return y;
}

typedef wmma::fragment<wmma::accumulator, 16, 16, 16, float>  AccH;
typedef wmma::fragment<wmma::accumulator, 16, 16, 16, __half> AccHF;
typedef wmma::fragment<wmma::matrix_a, 16, 16, 16, __half, wmma::row_major> AH;
typedef wmma::fragment<wmma::matrix_b, 16, 16, 16, __half, wmma::row_major> BH;

// ===========================================================================
// kCvtAll: all five fp32 -> fp16 conversions in one launch, 4 float4/thread.
// ===========================================================================
__global__ void kCvtAll(const float4* __restrict__ x0, const float4* __restrict__ v0,
                        const float4* __restrict__ F,  const float4* __restrict__ U,
                        const float4* __restrict__ W,
                        __half2* __restrict__ Xh, __half2* __restrict__ Vh,
                        __half2* __restrict__ Fh, __half2* __restrict__ Uh,
                        __half2* __restrict__ Wh)
{
    const int p = blockIdx.y;
    const float4* in; __half2* out; int n4;
    if      (p == 0) { in = x0; out = Xh; n4 = Bsz * Dd / 4; }
    else if (p == 1) { in = v0; out = Vh; n4 = Bsz * Dd / 4; }
    else if (p == 2) { in = F;  out = Fh; n4 = Bsz * Dd / 4; }
    else if (p == 3) { in = U;  out = Uh; n4 = Dd * Rr / 4; }
    else             { in = W;  out = Wh; n4 = Rr * Dd / 4; }

    int i = blockIdx.x * 1024 + threadIdx.x;
    #pragma unroll
    for (int k = 0; k < 4; k++, i += 256) {
        if (i < n4) {
            float4 f = in[i];
            out[2 * i]     = __floats2half2_rn(f.x, f.y);
            out[2 * i + 1] = __floats2half2_rn(f.z, f.w);
        }
    }
}

// ===========================================================================
// kWU: WU = Wh@Uh  [256,1024]@[1024,256], split-K (8 x 128). Grid (2,2,8).
// ===========================================================================
constexpr int W_LDA = 72;
constexpr int W_LDB = 136;
constexpr int W_STAGE_H = 128 * W_LDA + 64 * W_LDB;
constexpr int W_SMEM = 2 * W_STAGE_H * 2;

__global__ void __launch_bounds__(256, 1)
kWU()
{
    extern __shared__ __half smh[];
    const int bnn = blockIdx.x, bm = blockIdx.y, kz = blockIdx.z;
    const int tid = threadIdx.x, warp = tid >> 5;
    const int wRow = (warp & 3) * 32, wCol = (warp >> 2) * 64;

    AccH acc[2][4];
    #pragma unroll
    for (int i = 0; i < 2; i++)
        #pragma unroll
        for (int j = 0; j < 4; j++) wmma::fill_fragment(acc[i][j], 0.0f);

    const __half* Ag = g_Wh + (size_t)bm * 128 * Dd + kz * 128;
    const __half* Bg = g_Uh + (size_t)kz * 128 * Rr + bnn * 128;

    auto load_stage = [&](int kt, int s) {
        __half* sA = smh + s * W_STAGE_H;
        __half* sB = sA + 128 * W_LDA;
        const int k0 = kt * 64;
        #pragma unroll
        for (int it = 0; it < 4; it++) {
            int u = tid + it * 256;
            int r = u >> 3, c8 = u & 7;
            cp_async16(&sA[r * W_LDA + c8 * 8], Ag + (size_t)r * Dd + k0 + c8 * 8);
        }
        #pragma unroll
        for (int it = 0; it < 4; it++) {
            int u = tid + it * 256;
            int r = u >> 4, c8 = u & 15;
            cp_async16(&sB[r * W_LDB + c8 * 8], Bg + (size_t)(k0 + r) * Rr + c8 * 8);
        }
        cp_commit();
    };

    constexpr int KT = 2;
    load_stage(0, 0);
    for (int kt = 0; kt < KT; kt++) {
        if (kt + 1 < KT) { load_stage(kt + 1, (kt + 1) & 1); cp_wait<1>(); }
        else             { cp_wait<0>(); }
        __syncthreads();
        const __half* sA = smh + (kt & 1) * W_STAGE_H;
        const __half* sB = sA + 128 * W_LDA;
        #pragma unroll
        for (int kk = 0; kk < 4; kk++) {
            AH af[2]; BH bf[4];
            #pragma unroll
            for (int i = 0; i < 2; i++)
                wmma::load_matrix_sync(af[i], sA + (wRow + i * 16) * W_LDA + kk * 16, W_LDA);
            #pragma unroll
            for (int j = 0; j < 4; j++)
                wmma::load_matrix_sync(bf[j], sB + (kk * 16) * W_LDB + wCol + j * 16, W_LDB);
            #pragma unroll
            for (int i = 0; i < 2; i++)
                #pragma unroll
                for (int j = 0; j < 4; j++)
                    wmma::mma_sync(acc[i][j], af[i], bf[j], acc[i][j]);
        }
        __syncthreads();
    }

    float* out = g_WUp + (size_t)kz * Rr * Rr;
    #pragma unroll
    for (int i = 0; i < 2; i++)
        #pragma unroll
        for (int j = 0; j < 4; j++)
            wmma::store_matrix_sync(out + (size_t)(bm * 128 + wRow + i * 16) * Rr
                                        + bnn * 128 + wCol + j * 16,
                                    acc[i][j], Rr, wmma::mem_row_major);
}

__global__ void kRed() {
    int i = blockIdx.x * 256 + threadIdx.x;
    float s = 0.0f;
    #pragma unroll
    for (int z = 0; z < 8; z++) s += g_WUp[(size_t)z * Rr * Rr + i];
    g_WUh[i] = __float2half_rn(s);
}

// ===========================================================================
// kInit: hx = X@U, hv = V@U, fU = F@U. Tile 64x64, BK=64, grid (4,64), occ 2.
// ===========================================================================
constexpr int I_LDA = 72;
constexpr int I_LDU = 72;
constexpr int I_STAGE_H = 3 * 64 * I_LDA + 64 * I_LDU;
constexpr int I_SMEM = 2 * I_STAGE_H * 2;

__global__ void __launch_bounds__(256, 2)
kInit()
{
    extern __shared__ __half smh[];
    const int bn = blockIdx.x, bm = blockIdx.y;
    const int tid = threadIdx.x, warp = tid >> 5;
    const int wm = warp & 1, wn = warp >> 1;
    const int wRow = wm * 32, wCol = wn * 16;

    AccH acc[3][2];
    #pragma unroll
    for (int o = 0; o < 3; o++)
        #pragma unroll
        for (int i = 0; i < 2; i++) wmma::fill_fragment(acc[o][i], 0.0f);

    const __half* Ag[3] = { g_Xh + (size_t)bm * 64 * Dd,
                            g_Vh + (size_t)bm * 64 * Dd,
                            g_Fh + (size_t)bm * 64 * Dd };
    const __half* Ug = g_Uh + bn * 64;

    auto load_stage = [&](int kt, int s) {
        __half* st = smh + s * I_STAGE_H;
        const int k0 = kt * 64;
        #pragma unroll
        for (int o = 0; o < 3; o++) {
            __half* sA = st + o * 64 * I_LDA;
            #pragma unroll
            for (int it = 0; it < 2; it++) {
                int u = tid + it * 256;
                int r = u >> 3, c8 = u & 7;
                cp_async16(&sA[r * I_LDA + c8 * 8], Ag[o] + (size_t)r * Dd + k0 + c8 * 8);
            }
        }
        __half* sU = st + 3 * 64 * I_LDA;
        #pragma unroll
        for (int it = 0; it < 2; it++) {
            int u = tid + it * 256;
            int r = u >> 3, c8 = u & 7;
            cp_async16(&sU[r * I_LDU + c8 * 8], Ug + (size_t)(k0 + r) * Rr + c8 * 8);
        }
        cp_commit();
    };

    constexpr int KT = Dd / 64;
    load_stage(0, 0);
    for (int kt = 0; kt < KT; kt++) {
        if (kt + 1 < KT) { load_stage(kt + 1, (kt + 1) & 1); cp_wait<1>(); }
        else             { cp_wait<0>(); }
        __syncthreads();
        const __half* st = smh + (kt & 1) * I_STAGE_H;
        const __half* sU = st + 3 * 64 * I_LDA;
        #pragma unroll
        for (int kk = 0; kk < 4; kk++) {
            BH bu;
            wmma::load_matrix_sync(bu, sU + (kk * 16) * I_LDU + wCol, I_LDU);
            #pragma unroll
            for (int o = 0; o < 3; o++) {
                #pragma unroll
                for (int i = 0; i < 2; i++) {
                    AH af;
                    wmma::load_matrix_sync(af,
                        st + o * 64 * I_LDA + (wRow + i * 16) * I_LDA + kk * 16, I_LDA);
                    wmma::mma_sync(acc[o][i], af, bu, acc[o][i]);
                }
            }
        }
        __syncthreads();
    }

    #pragma unroll
    for (int i = 0; i < 2; i++) {
        size_t off = (size_t)(bm * 64 + wRow + i * 16) * Rr + bn * 64 + wCol;
        wmma::store_matrix_sync(g_hx + off, acc[0][i], Rr, wmma::mem_row_major);
        wmma::store_matrix_sync(g_hv + off, acc[1][i], Rr, wmma::mem_row_major);
        wmma::store_matrix_sync(g_fU + off, acc[2][i], Rr, wmma::mem_row_major);
        #pragma unroll
        for (int e = 0; e < acc[0][i].num_elements; e++) {
            float h = acc[1][i].x[e];
            acc[0][i].x[e] = tanh_fast(acc[0][i].x[e]) * h * h;
        }
        wmma::store_matrix_sync(g_P + off, acc[0][i], Rr, wmma::mem_row_major);
    }
}

// ===========================================================================
// kSteps: persistent — 15 half-steps AND the final dual GEMM + output, fused.
// 128 CTAs x 256 thr; CTA owns 32 batch rows end-to-end.
// ===========================================================================
constexpr int PLD = 264;
constexpr int WLD = 72;
constexpr size_t PSB_WU = 0;                               // 256*264*2 = 135168 B
constexpr size_t PSB_HV = PSB_WU + 256 * PLD * 2;
constexpr size_t PSB_HX = PSB_HV + 32 * 256 * 4;
constexpr size_t PSB_P  = PSB_HX + 32 * 256 * 4;
constexpr size_t PS_SMEM = PSB_P + 32 * PLD * 2;           // 217600 B

// phase-2 layout inside the WU region:
constexpr size_t F2_SX = 0;                     // halves offsets within WU region
constexpr size_t F2_SV = F2_SX + 32 * PLD;
constexpr size_t F2_WT = F2_SV + 32 * PLD;      // 2 buffers of 256*WLD
constexpr size_t F2_G  = F2_WT + 2 * 256 * WLD; // 2 arrays of 32*WLD

__global__ void __launch_bounds__(256, 1)
kSteps(const float* __restrict__ x0, const float* __restrict__ v0,
       const float* __restrict__ Fin, float* __restrict__ Xw, float* __restrict__ Vw)
{
    extern __shared__ char smc[];
    __half* sWU = (__half*)(smc + PSB_WU);
    float*  sHv = (float*)(smc + PSB_HV);
    float*  sHx = (float*)(smc + PSB_HX);
    __half* sP  = (__half*)(smc + PSB_P);

    const int tid  = threadIdx.x;
    const int warp = tid >> 5;
    const int wm = warp & 1, wn = warp >> 1;
    const int base = blockIdx.x * 32;

    #pragma unroll
    for (int it = 0; it < 32; it++) {
        int u = tid + it * 256;
        int r = u >> 5, c8 = u & 31;
        cp_async16(&sWU[r * PLD + c8 * 8], g_WUh + (size_t)r * Rr + c8 * 8);
    }
    cp_commit();

    #pragma unroll
    for (int it = 0; it < 8; it++) {
        int u = tid + it * 256;
        int r = u >> 6, c = (u & 63) * 4;
        size_t g = (size_t)(base + r) * Rr + c;
        *(float4*)&sHv[r * 256 + c] = *(const float4*)(g_hv + g);
        *(float4*)&sHx[r * 256 + c] = *(const float4*)(g_hx + g);
        float4 p = *(const float4*)(g_P + g);
        *(__half2*)&sP[r * PLD + c]     = __floats2half2_rn(p.x, p.y);
        *(__half2*)&sP[r * PLD + c + 2] = __floats2half2_rn(p.z, p.w);
    }

    const int rt  = tid >> 3;
    const int ct0 = (tid & 7) * 4;
    float fu[32];
    #pragma unroll
    for (int j = 0; j < 8; j++) {
        float4 f = *(const float4*)(g_fU + (size_t)(base + rt) * Rr + ct0 + j * 32);
        fu[j*4+0] = f.x; fu[j*4+1] = f.y; fu[j*4+2] = f.z; fu[j*4+3] = f.w;
    }

    cp_wait<0>();
    __syncthreads();

    float Sv[32], Sx[32];
    #pragma unroll
    for (int j = 0; j < 8; j++) {
        int o = rt * PLD + ct0 + j * 32;
        #pragma unroll
        for (int q = 0; q < 4; q++) {
            float p = __half2float(sP[o + q]);
            Sv[j*4+q] = p; Sx[j*4+q] = 8.0f * p;
        }
    }

    // ---------------- phase 1: 15 half-steps ----------------
    #pragma unroll 1
    for (int t = 0; t < 15; t++) {
        AccHF acc[4];
        #pragma unroll
        for (int j = 0; j < 4; j++) wmma::fill_fragment(acc[j], (__half)0.0f);

        #pragma unroll
        for (int k = 0; k < 16; k++) {
            AH a;
            wmma::load_matrix_sync(a, &sP[(wm * 16) * PLD + k * 16], PLD);
            #pragma unroll
            for (int j = 0; j < 4; j++) {
                BH bf;
                wmma::load_matrix_sync(bf, &sWU[(k * 16) * PLD + wn * 64 + j * 16], PLD);
                wmma::mma_sync(acc[j], a, bf, acc[j]);
            }
        }
        __syncthreads();

        #pragma unroll
        for (int j = 0; j < 4; j++)
            wmma::store_matrix_sync(&sP[(wm * 16) * PLD + wn * 64 + j * 16],
                                    acc[j], PLD, wmma::mem_row_major);
        __syncthreads();

        const float wq  = (float)(7 - (t >> 1));
        const bool updx = (t & 1) == 0;
        #pragma unroll
        for (int j = 0; j < 8; j++) {
            int oh = rt * PLD + ct0 + j * 32;
            int of = rt * 256 + ct0 + j * 32;
            float2 g0 = __half22float2(*(__half2*)&sP[oh]);
            float2 g1 = __half22float2(*(__half2*)&sP[oh + 2]);
            float4 hv = *(float4*)&sHv[of];
            hv.x += 0.005f * (fu[j*4+0] - g0.x);
            hv.y += 0.005f * (fu[j*4+1] - g0.y);
            hv.z += 0.005f * (fu[j*4+2] - g1.x);
            hv.w += 0.005f * (fu[j*4+3] - g1.y);
            *(float4*)&sHv[of] = hv;
            float4 hx = *(float4*)&sHx[of];
            if (updx) {
                hx.x += 0.01f * hv.x; hx.y += 0.01f * hv.y;
                hx.z += 0.01f * hv.z; hx.w += 0.01f * hv.w;
                *(float4*)&sHx[of] = hx;
            }
            float4 p;
            p.x = tanh_fast(hx.x) * hv.x * hv.x;
            p.y = tanh_fast(hx.y) * hv.y * hv.y;
            p.z = tanh_fast(hx.z) * hv.z * hv.z;
            p.w = tanh_fast(hx.w) * hv.w * hv.w;
            *(__half2*)&sP[oh]     = __floats2half2_rn(p.x, p.y);
            *(__half2*)&sP[oh + 2] = __floats2half2_rn(p.z, p.w);
            Sv[j*4+0] += p.x; Sv[j*4+1] += p.y; Sv[j*4+2] += p.z; Sv[j*4+3] += p.w;
            Sx[j*4+0] += wq * p.x; Sx[j*4+1] += wq * p.y;
            Sx[j*4+2] += wq * p.z; Sx[j*4+3] += wq * p.w;
        }
        __syncthreads();
    }

    // ---------------- phase 2: fused final dual GEMM + output ----------------
    __half* sSx = sWU + F2_SX;
    __half* sSv = sWU + F2_SV;
    __half* sWt = sWU + F2_WT;          // 2 buffers of 256*WLD
    __half* sGx = sWU + F2_G;           // 32*WLD
    __half* sGv = sGx + 32 * WLD;

    auto loadWt = [&](int nt, int b) {
        __half* dst = sWt + (size_t)b * 256 * WLD;
        // 256 rows x 64 cols of W: 2048 transactions of 8 halves
        #pragma unroll
        for (int it = 0; it < 8; it++) {
            int u = tid + it * 256;
            int r = u >> 3, c8 = u & 7;          // r: 0..255, c8: 0..7  (FIXED)
            cp_async16(&dst[r * WLD + c8 * 8], g_Wh + (size_t)r * Dd + nt * 64 + c8 * 8);
        }
        cp_commit();
    };

    loadWt(0, 0);   // overlap with Sx/Sv conversion

    // convert register sums -> half A-matrices (each thread owns its own slots)
    #pragma unroll
    for (int j = 0; j < 8; j++) {
        int o = rt * PLD + ct0 + j * 32;
        *(__half2*)&sSx[o]     = __floats2half2_rn(Sx[j*4+0], Sx[j*4+1]);
        *(__half2*)&sSx[o + 2] = __floats2half2_rn(Sx[j*4+2], Sx[j*4+3]);
        *(__half2*)&sSv[o]     = __floats2half2_rn(Sv[j*4+0], Sv[j*4+1]);
        *(__half2*)&sSv[o + 2] = __floats2half2_rn(Sv[j*4+2], Sv[j*4+3]);
    }
    __syncthreads();

    const float c_xv = 0.08f;        // 8*dt
    const float c_xf = 0.0032f;      // 64*dt*hdt
    const float c_xg = 5e-5f;        // dt*hdt
    const float c_vf = 0.08f;        // 16*hdt
    const float c_vg = 0.005f;       // hdt

    #pragma unroll 1
    for (int nt = 0; nt < 16; nt++) {
        if (nt + 1 < 16) { loadWt(nt + 1, (nt + 1) & 1); cp_wait<1>(); }
        else             { cp_wait<0>(); }
        __syncthreads();
        const __half* sW = sWt + (size_t)(nt & 1) * 256 * WLD;

        // gamma_x, gamma_v [32,64] = (Sx|Sv)[32,256] @ W[256, nt*64 .. +64]
        AccHF ax, av;
        wmma::fill_fragment(ax, (__half)0.0f);
        wmma::fill_fragment(av, (__half)0.0f);
        #pragma unroll
        for (int k = 0; k < 16; k++) {
            BH bf;
            wmma::load_matrix_sync(bf, sW + (k * 16) * WLD + wn * 16, WLD);
            AH a;
            wmma::load_matrix_sync(a, &sSx[(wm * 16) * PLD + k * 16], PLD);
            wmma::mma_sync(ax, a, bf, ax);
            wmma::load_matrix_sync(a, &sSv[(wm * 16) * PLD + k * 16], PLD);
            wmma::mma_sync(av, a, bf, av);
        }
        wmma::store_matrix_sync(&sGx[(wm * 16) * WLD + wn * 16], ax, WLD, wmma::mem_row_major);
        wmma::store_matrix_sync(&sGv[(wm * 16) * WLD + wn * 16], av, WLD, wmma::mem_row_major);
        __syncthreads();

        // fused output for these 64 columns: 32 rows x 64 cols, 8 cols/thread
        {
            int r  = tid >> 3;
            int c0 = (tid & 7) * 8;
            size_t idx = (size_t)(base + r) * Dd + nt * 64 + c0;
            #pragma unroll
            for (int h = 0; h < 2; h++) {
                float2 gx0 = __half22float2(*(__half2*)&sGx[r * WLD + c0 + h * 4]);
                float2 gx1 = __half22float2(*(__half2*)&sGx[r * WLD + c0 + h * 4 + 2]);
                float2 gv0 = __half22float2(*(__half2*)&sGv[r * WLD + c0 + h * 4]);
                float2 gv1 = __half22float2(*(__half2*)&sGv[r * WLD + c0 + h * 4 + 2]);
                float4 x = *(const float4*)(x0 + idx + h * 4);
                float4 v = *(const float4*)(v0 + idx + h * 4);
                float4 f = *(const float4*)(Fin + idx + h * 4);
                float4 xo, vo;
                xo.x = x.x + c_xv * v.x + c_xf * f.x - c_xg * gx0.x;
                xo.y = x.y + c_xv * v.y + c_xf * f.y - c_xg * gx0.y;
                xo.z = x.z + c_xv * v.z + c_xf * f.z - c_xg * gx1.x;
                xo.w = x.w + c_xv * v.w + c_xf * f.w - c_xg * gx1.y;
                vo.x = v.x + c_vf * f.x - c_vg * gv0.x;
                vo.y = v.y + c_vf * f.y - c_vg * gv0.y;
                vo.z = v.z + c_vf * f.z - c_vg * gv1.x;
                vo.w = v.w + c_vf * f.w - c_vg * gv1.y;
                *(float4*)(Xw + idx + h * 4) = xo;
                *(float4*)(Vw + idx + h * 4) = vo;
            }
        }
        __syncthreads();   // staging reused next tile
    }
}

// ===========================================================================
extern "C" void kernel_launch(void* const* d_in, const int* in_sizes, int n_in,
                              void* d_out, int out_size)
{
    const float* x0 = (const float*)d_in[0];
    const float* v0 = (const float*)d_in[1];
    const float* F  = (const float*)d_in[2];
    const float* U  = (const float*)d_in[3];
    const float* W  = (const float*)d_in[4];

    float* Xw = (float*)d_out;
    float* Vw = Xw + (size_t)Bsz * Dd;

    cudaFuncSetAttribute(kWU,    cudaFuncAttributeMaxDynamicSharedMemorySize, W_SMEM);
    cudaFuncSetAttribute(kInit,  cudaFuncAttributeMaxDynamicSharedMemorySize, I_SMEM);
    cudaFuncSetAttribute(kSteps, cudaFuncAttributeMaxDynamicSharedMemorySize, (int)PS_SMEM);

    void *pXh, *pVh, *pFh, *pUh, *pWh;
    cudaGetSymbolAddress(&pXh, g_Xh);
    cudaGetSymbolAddress(&pVh, g_Vh);
    cudaGetSymbolAddress(&pFh, g_Fh);
    cudaGetSymbolAddress(&pUh, g_Uh);
    cudaGetSymbolAddress(&pWh, g_Wh);

    dim3 blk(256);

    kCvtAll<<<dim3(1024, 5), blk>>>((const float4*)x0, (const float4*)v0,
                                    (const float4*)F,  (const float4*)U,
                                    (const float4*)W,
                                    (__half2*)pXh, (__half2*)pVh, (__half2*)pFh,
                                    (__half2*)pUh, (__half2*)pWh);

    kWU<<<dim3(2, 2, 8), blk, W_SMEM>>>();
    kRed<<<Rr * Rr / 256, 256>>>();
    kInit<<<dim3(4, 64), blk, I_SMEM>>>();
    kSteps<<<128, blk, PS_SMEM>>>(x0, v0, F, Xw, Vw);
}